// round 1
// baseline (speedup 1.0000x reference)
#include <cuda_runtime.h>

#define CTX  2048
#define EMB  1024
#define NH   16
#define HD   64
#define BT   8192   // B*T = 4*2048

// Scratch (allocation-free rule: __device__ globals)
__device__ float g_q[BT * EMB];
__device__ float g_k[BT * EMB];
__device__ float g_v[BT * EMB];
__device__ float g_a[BT * EMB];

// ---------------------------------------------------------------------------
// GEMM: C[m,n] = sum_k A[m,k] * W[n,k] + bias[n]
// A: (8192 x 1024) row-major, W: (1024 x 1024) row-major (torch Linear weight)
// MODE 0: C row-major (8192 x 1024)
// MODE 1: scatter to (B,H,T,D) layout for attention
// 128x128 block tile, 16 K-tile, 256 threads, 8x8 per-thread micro-tile.
// Both operands stored K-transposed in smem => float4 LDS, conflict-free.
// ---------------------------------------------------------------------------
template <int MODE>
__global__ __launch_bounds__(256)
void gemm_kernel(const float* __restrict__ A, const float* __restrict__ W,
                 const float* __restrict__ bias, float* __restrict__ C) {
    __shared__ float Ats[16 * 132];   // [k][m], stride 132 (33 float4)
    __shared__ float Bts[16 * 132];   // [k][n]

    const int tid = threadIdx.x;
    const int tx = tid & 15;          // n direction
    const int ty = tid >> 4;          // m direction
    const int m0 = blockIdx.y * 128;
    const int n0 = blockIdx.x * 128;

    float acc[8][8];
#pragma unroll
    for (int i = 0; i < 8; i++)
#pragma unroll
        for (int j = 0; j < 8; j++) acc[i][j] = 0.f;

    for (int k0 = 0; k0 < EMB; k0 += 16) {
        __syncthreads();
        // 128 rows x 16 k = 512 float4 per operand, 2 per thread
#pragma unroll
        for (int t = tid; t < 512; t += 256) {
            const int row = t >> 2;
            const int k4  = (t & 3) * 4;
            float4 av = *(const float4*)(A + (size_t)(m0 + row) * EMB + k0 + k4);
            Ats[(k4 + 0) * 132 + row] = av.x;
            Ats[(k4 + 1) * 132 + row] = av.y;
            Ats[(k4 + 2) * 132 + row] = av.z;
            Ats[(k4 + 3) * 132 + row] = av.w;
            float4 wv = *(const float4*)(W + (size_t)(n0 + row) * EMB + k0 + k4);
            Bts[(k4 + 0) * 132 + row] = wv.x;
            Bts[(k4 + 1) * 132 + row] = wv.y;
            Bts[(k4 + 2) * 132 + row] = wv.z;
            Bts[(k4 + 3) * 132 + row] = wv.w;
        }
        __syncthreads();

#pragma unroll
        for (int kk = 0; kk < 16; kk++) {
            float a[8], b[8];
            *(float4*)(a)     = *(const float4*)(Ats + kk * 132 + ty * 8);
            *(float4*)(a + 4) = *(const float4*)(Ats + kk * 132 + ty * 8 + 4);
            *(float4*)(b)     = *(const float4*)(Bts + kk * 132 + tx * 8);
            *(float4*)(b + 4) = *(const float4*)(Bts + kk * 132 + tx * 8 + 4);
#pragma unroll
            for (int i = 0; i < 8; i++)
#pragma unroll
                for (int j = 0; j < 8; j++)
                    acc[i][j] += a[i] * b[j];
        }
    }

#pragma unroll
    for (int i = 0; i < 8; i++) {
        const int m = m0 + ty * 8 + i;
#pragma unroll
        for (int j4 = 0; j4 < 8; j4 += 4) {
            const int n = n0 + tx * 8 + j4;
            float4 r;
            r.x = acc[i][j4 + 0] + bias[n + 0];
            r.y = acc[i][j4 + 1] + bias[n + 1];
            r.z = acc[i][j4 + 2] + bias[n + 2];
            r.w = acc[i][j4 + 3] + bias[n + 3];
            if (MODE == 0) {
                *(float4*)(C + (size_t)m * EMB + n) = r;
            } else {
                const int b_ = m >> 11;        // m / 2048
                const int t  = m & 2047;
                const int h  = n >> 6;         // n / 64
                const int d  = n & 63;
                *(float4*)(C + (((size_t)(b_ * NH + h) * CTX + t) * HD + d)) = r;
            }
        }
    }
}

// ---------------------------------------------------------------------------
// Flash attention (causal), fp32.
// One block = one (b,h) x one 64-query tile. 256 threads, 16x16 (tx,ty),
// each thread owns a 4(row) x 4(col/dim) micro-tile.
// Online softmax; only the diagonal key tile is masked.
// smem: Qt[d][r], Kt[d][c], Vs[c][d], Ps[r][c], all stride 68.
// ---------------------------------------------------------------------------
#define ASTR 68
#define ATTN_SMEM (4 * 64 * ASTR * 4)

__global__ __launch_bounds__(256)
void attn_kernel(const float* __restrict__ q, const float* __restrict__ k,
                 const float* __restrict__ v, float* __restrict__ o) {
    extern __shared__ float sm[];
    float* Qt = sm;                   // [d][r]
    float* Kt = sm + 64 * ASTR;       // [d][c]
    float* Vs = sm + 2 * 64 * ASTR;   // [c][d]
    float* Ps = sm + 3 * 64 * ASTR;   // [r][c]

    const int tid = threadIdx.x;
    const int tx = tid & 15;
    const int ty = tid >> 4;
    const int bh = blockIdx.y;        // b*16 + h
    const int qt = blockIdx.x;        // query tile

    const float* qbase = q + ((size_t)bh * CTX + qt * 64) * HD;
    const float* kbase = k + (size_t)bh * CTX * HD;
    const float* vbase = v + (size_t)bh * CTX * HD;

    // Load Q tile transposed into smem
    for (int idx = tid; idx < 64 * 16; idx += 256) {
        const int r  = idx >> 4;
        const int d4 = (idx & 15) * 4;
        float4 vv = *(const float4*)(qbase + r * HD + d4);
        Qt[(d4 + 0) * ASTR + r] = vv.x;
        Qt[(d4 + 1) * ASTR + r] = vv.y;
        Qt[(d4 + 2) * ASTR + r] = vv.z;
        Qt[(d4 + 3) * ASTR + r] = vv.w;
    }

    float m_i[4], l_i[4], acc[4][4];
#pragma unroll
    for (int i = 0; i < 4; i++) {
        m_i[i] = -1e30f;
        l_i[i] = 0.f;
#pragma unroll
        for (int j = 0; j < 4; j++) acc[i][j] = 0.f;
    }

    for (int kt = 0; kt <= qt; kt++) {
        __syncthreads();
        // Load K (transposed) and V tiles
        for (int idx = tid; idx < 64 * 16; idx += 256) {
            const int c  = idx >> 4;
            const int d4 = (idx & 15) * 4;
            float4 kv = *(const float4*)(kbase + (size_t)(kt * 64 + c) * HD + d4);
            Kt[(d4 + 0) * ASTR + c] = kv.x;
            Kt[(d4 + 1) * ASTR + c] = kv.y;
            Kt[(d4 + 2) * ASTR + c] = kv.z;
            Kt[(d4 + 3) * ASTR + c] = kv.w;
            float4 vv = *(const float4*)(vbase + (size_t)(kt * 64 + c) * HD + d4);
            *(float4*)(Vs + c * ASTR + d4) = vv;
        }
        __syncthreads();

        // S = Q K^T (4x4 per thread)
        float s[4][4];
#pragma unroll
        for (int i = 0; i < 4; i++)
#pragma unroll
            for (int j = 0; j < 4; j++) s[i][j] = 0.f;

#pragma unroll 8
        for (int kk = 0; kk < 64; kk++) {
            float4 a4 = *(const float4*)(Qt + kk * ASTR + ty * 4);
            float4 b4 = *(const float4*)(Kt + kk * ASTR + tx * 4);
            const float a[4] = {a4.x, a4.y, a4.z, a4.w};
            const float b[4] = {b4.x, b4.y, b4.z, b4.w};
#pragma unroll
            for (int i = 0; i < 4; i++)
#pragma unroll
                for (int j = 0; j < 4; j++)
                    s[i][j] += a[i] * b[j];
        }

        const float sc = 0.125f;   // 1/sqrt(64)
        const bool diag = (kt == qt);
#pragma unroll
        for (int i = 0; i < 4; i++)
#pragma unroll
            for (int j = 0; j < 4; j++) {
                s[i][j] *= sc;
                if (diag && (tx * 4 + j) > (ty * 4 + i)) s[i][j] = -1e30f;
            }

        // row max across 4 local cols, then across 16 tx lanes
        float rm[4];
#pragma unroll
        for (int i = 0; i < 4; i++) {
            rm[i] = fmaxf(fmaxf(s[i][0], s[i][1]), fmaxf(s[i][2], s[i][3]));
#pragma unroll
            for (int msk = 1; msk < 16; msk <<= 1)
                rm[i] = fmaxf(rm[i], __shfl_xor_sync(0xffffffffu, rm[i], msk));
        }

        float scale[4], rs[4];
#pragma unroll
        for (int i = 0; i < 4; i++) {
            const float mnew = fmaxf(m_i[i], rm[i]);
            scale[i] = __expf(m_i[i] - mnew);
            m_i[i] = mnew;
            rs[i] = 0.f;
#pragma unroll
            for (int j = 0; j < 4; j++) {
                const float p = __expf(s[i][j] - mnew);
                s[i][j] = p;
                rs[i] += p;
            }
#pragma unroll
            for (int msk = 1; msk < 16; msk <<= 1)
                rs[i] += __shfl_xor_sync(0xffffffffu, rs[i], msk);
            l_i[i] = l_i[i] * scale[i] + rs[i];
#pragma unroll
            for (int j = 0; j < 4; j++) acc[i][j] *= scale[i];
        }

        // write P to smem
#pragma unroll
        for (int i = 0; i < 4; i++)
            *(float4*)(Ps + (ty * 4 + i) * ASTR + tx * 4) =
                make_float4(s[i][0], s[i][1], s[i][2], s[i][3]);
        __syncthreads();

        // O += P V
#pragma unroll 8
        for (int c = 0; c < 64; c++) {
            float4 b4 = *(const float4*)(Vs + c * ASTR + tx * 4);
            float a0 = Ps[(ty * 4 + 0) * ASTR + c];
            float a1 = Ps[(ty * 4 + 1) * ASTR + c];
            float a2 = Ps[(ty * 4 + 2) * ASTR + c];
            float a3 = Ps[(ty * 4 + 3) * ASTR + c];
            acc[0][0] += a0 * b4.x; acc[0][1] += a0 * b4.y; acc[0][2] += a0 * b4.z; acc[0][3] += a0 * b4.w;
            acc[1][0] += a1 * b4.x; acc[1][1] += a1 * b4.y; acc[1][2] += a1 * b4.z; acc[1][3] += a1 * b4.w;
            acc[2][0] += a2 * b4.x; acc[2][1] += a2 * b4.y; acc[2][2] += a2 * b4.z; acc[2][3] += a2 * b4.w;
            acc[3][0] += a3 * b4.x; acc[3][1] += a3 * b4.y; acc[3][2] += a3 * b4.z; acc[3][3] += a3 * b4.w;
        }
    }

    // normalize and write to (B,T,N) layout
    const int b_ = bh >> 4;
    const int h  = bh & 15;
#pragma unroll
    for (int i = 0; i < 4; i++) {
        const int t = qt * 64 + ty * 4 + i;
        const float inv = 1.f / l_i[i];
        float4 r = make_float4(acc[i][0] * inv, acc[i][1] * inv,
                               acc[i][2] * inv, acc[i][3] * inv);
        *(float4*)(o + ((size_t)(b_ * CTX + t)) * EMB + h * HD + tx * 4) = r;
    }
}

// ---------------------------------------------------------------------------
extern "C" void kernel_launch(void* const* d_in, const int* in_sizes, int n_in,
                              void* d_out, int out_size) {
    const float* x  = (const float*)d_in[0];
    const float* Wq = (const float*)d_in[1];
    const float* bq = (const float*)d_in[2];
    const float* Wk = (const float*)d_in[3];
    const float* bk = (const float*)d_in[4];
    const float* Wv = (const float*)d_in[5];
    const float* bv = (const float*)d_in[6];
    const float* Wp = (const float*)d_in[7];
    const float* bp = (const float*)d_in[8];

    float *q, *k, *v, *a;
    cudaGetSymbolAddress((void**)&q, g_q);
    cudaGetSymbolAddress((void**)&k, g_k);
    cudaGetSymbolAddress((void**)&v, g_v);
    cudaGetSymbolAddress((void**)&a, g_a);

    dim3 ggrid(EMB / 128, BT / 128);   // (8, 64)
    gemm_kernel<1><<<ggrid, 256>>>(x, Wq, bq, q);
    gemm_kernel<1><<<ggrid, 256>>>(x, Wk, bk, k);
    gemm_kernel<1><<<ggrid, 256>>>(x, Wv, bv, v);

    cudaFuncSetAttribute(attn_kernel,
                         cudaFuncAttributeMaxDynamicSharedMemorySize, ATTN_SMEM);
    attn_kernel<<<dim3(CTX / 64, 4 * NH), 256, ATTN_SMEM>>>(q, k, v, a);

    gemm_kernel<0><<<ggrid, 256>>>(a, Wp, bp, (float*)d_out);
}

// round 3
// speedup vs baseline: 4.7953x; 4.7953x over previous
#include <cuda_runtime.h>
#include <cstdint>

#define CTX  2048
#define EMB  1024
#define NH   16
#define HD   64
#define BT   8192   // B*T

// Scratch (allocation-free rule: __device__ globals)
__device__ float g_q[BT * EMB];
__device__ float g_k[BT * EMB];
__device__ float g_v[BT * EMB];
__device__ float g_a[BT * EMB];

// ======================= mma.sync tf32 helpers =============================
__device__ __forceinline__ uint32_t f2tf(float f) {
    uint32_t u;
    asm("cvt.rna.tf32.f32 %0, %1;" : "=r"(u) : "f"(f));
    return u;
}
// D(16x8,f32) += A(16x8,tf32,row) * B(8x8,tf32,col)
__device__ __forceinline__ void mma_tf32(float* d, const uint32_t* a,
                                         const uint32_t* b) {
    asm volatile(
        "mma.sync.aligned.m16n8k8.row.col.f32.tf32.tf32.f32 "
        "{%0,%1,%2,%3}, {%4,%5,%6,%7}, {%8,%9}, {%0,%1,%2,%3};"
        : "+f"(d[0]), "+f"(d[1]), "+f"(d[2]), "+f"(d[3])
        : "r"(a[0]), "r"(a[1]), "r"(a[2]), "r"(a[3]), "r"(b[0]), "r"(b[1]));
}

// ---------------------------------------------------------------------------
// GEMM: C[m,n] = sum_k A[m,k] * W[n,k] + bias[n]   (A: 8192x1024, W: 1024x1024)
// 128x128 CTA tile, 256 thr / 8 warps, warp tile 64x32 (4 m-atoms x 4 n-atoms),
// K chunks of 32 (4 k8 steps). tf32 via cvt.rna at smem staging.
// MODE 0: row-major out.  MODE 1: scatter to (B,H,T,D).
// ---------------------------------------------------------------------------
#define ASTRIDE 36

template <int MODE>
__global__ __launch_bounds__(256)
void gemm_tc(const float* __restrict__ A, const float* __restrict__ W,
             const float* __restrict__ bias, float* __restrict__ C) {
    __shared__ uint32_t As[128 * ASTRIDE];
    __shared__ uint32_t Bs[128 * ASTRIDE];

    const int tid  = threadIdx.x;
    const int wid  = tid >> 5;
    const int lane = tid & 31;
    const int g    = lane >> 2;   // group id (row within atom)
    const int t    = lane & 3;    // thread in group (col within k8)
    const int wm0  = (wid >> 2) * 64;
    const int wn0  = (wid & 3) * 32;
    const int m0   = blockIdx.y * 128;
    const int n0   = blockIdx.x * 128;

    float acc[4][4][4];
#pragma unroll
    for (int mi = 0; mi < 4; mi++)
#pragma unroll
        for (int ni = 0; ni < 4; ni++)
#pragma unroll
            for (int c = 0; c < 4; c++) acc[mi][ni][c] = 0.f;

    // prefetch chunk 0 into registers
    float4 ra[4], rb[4];
#pragma unroll
    for (int i = 0; i < 4; i++) {
        const int it = tid + i * 256;
        const int row = it >> 3;
        const int kv = it & 7;
        ra[i] = *(const float4*)(A + (size_t)(m0 + row) * EMB + kv * 4);
        rb[i] = *(const float4*)(W + (size_t)(n0 + row) * EMB + kv * 4);
    }

    for (int c = 0; c < 32; c++) {
        __syncthreads();   // prior compute done reading smem
#pragma unroll
        for (int i = 0; i < 4; i++) {
            const int it = tid + i * 256;
            const int row = it >> 3;
            const int kv = it & 7;
            *(uint4*)(As + row * ASTRIDE + kv * 4) =
                make_uint4(f2tf(ra[i].x), f2tf(ra[i].y), f2tf(ra[i].z), f2tf(ra[i].w));
            *(uint4*)(Bs + row * ASTRIDE + kv * 4) =
                make_uint4(f2tf(rb[i].x), f2tf(rb[i].y), f2tf(rb[i].z), f2tf(rb[i].w));
        }
        __syncthreads();
        if (c < 31) {
            const int k0 = (c + 1) * 32;
#pragma unroll
            for (int i = 0; i < 4; i++) {
                const int it = tid + i * 256;
                const int row = it >> 3;
                const int kv = it & 7;
                ra[i] = *(const float4*)(A + (size_t)(m0 + row) * EMB + k0 + kv * 4);
                rb[i] = *(const float4*)(W + (size_t)(n0 + row) * EMB + k0 + kv * 4);
            }
        }
#pragma unroll
        for (int ks = 0; ks < 4; ks++) {
            const int kc = ks * 8;
            uint32_t afr[4][4];
#pragma unroll
            for (int mi = 0; mi < 4; mi++) {
                const int rb_ = wm0 + mi * 16;
                afr[mi][0] = As[(rb_ + g) * ASTRIDE + kc + t];
                afr[mi][1] = As[(rb_ + g + 8) * ASTRIDE + kc + t];
                afr[mi][2] = As[(rb_ + g) * ASTRIDE + kc + t + 4];
                afr[mi][3] = As[(rb_ + g + 8) * ASTRIDE + kc + t + 4];
            }
            uint32_t bfr[4][2];
#pragma unroll
            for (int ni = 0; ni < 4; ni++) {
                const int nb = wn0 + ni * 8;
                bfr[ni][0] = Bs[(nb + g) * ASTRIDE + kc + t];
                bfr[ni][1] = Bs[(nb + g) * ASTRIDE + kc + t + 4];
            }
#pragma unroll
            for (int mi = 0; mi < 4; mi++)
#pragma unroll
                for (int ni = 0; ni < 4; ni++)
                    mma_tf32(acc[mi][ni], afr[mi], bfr[ni]);
        }
    }

    // epilogue
#pragma unroll
    for (int mi = 0; mi < 4; mi++) {
        const int r_lo = m0 + wm0 + mi * 16 + g;
        const int r_hi = r_lo + 8;
#pragma unroll
        for (int ni = 0; ni < 4; ni++) {
            const int n = n0 + wn0 + ni * 8 + 2 * t;
            const float2 b2 = *(const float2*)(bias + n);
            float2 lo = make_float2(acc[mi][ni][0] + b2.x, acc[mi][ni][1] + b2.y);
            float2 hi = make_float2(acc[mi][ni][2] + b2.x, acc[mi][ni][3] + b2.y);
            if (MODE == 0) {
                *(float2*)(C + (size_t)r_lo * EMB + n) = lo;
                *(float2*)(C + (size_t)r_hi * EMB + n) = hi;
            } else {
                const int h = n >> 6, d = n & 63;
                const int b1_ = r_lo >> 11, t1 = r_lo & 2047;
                const int b2_ = r_hi >> 11, t2 = r_hi & 2047;
                *(float2*)(C + (((size_t)(b1_ * NH + h) * CTX + t1) * HD + d)) = lo;
                *(float2*)(C + (((size_t)(b2_ * NH + h) * CTX + t2) * HD + d)) = hi;
            }
        }
    }
}

// ---------------------------------------------------------------------------
// Flash attention (causal) with mma.sync tf32.
// Block: 128 thr / 4 warps, 64 queries (16 rows per warp). Key tiles of 64.
// Q lives in A-fragments (scale folded). K,V,P staged in smem (stride 68).
// ---------------------------------------------------------------------------
#define KSTR 68
#define ATTN_SMEM (3 * 64 * KSTR * 4)

__global__ __launch_bounds__(128)
void attn_kernel(const float* __restrict__ q, const float* __restrict__ k,
                 const float* __restrict__ v, float* __restrict__ o) {
    extern __shared__ uint32_t sm_[];
    uint32_t* Ks = sm_;
    uint32_t* Vs = sm_ + 64 * KSTR;
    uint32_t* Ps = sm_ + 2 * 64 * KSTR;

    const int tid  = threadIdx.x;
    const int wid  = tid >> 5;
    const int lane = tid & 31;
    const int g    = lane >> 2;
    const int t    = lane & 3;
    const int bh   = blockIdx.y;
    const int qt   = blockIdx.x;
    const int q0   = qt * 64 + wid * 16;

    const float* qbase = q + ((size_t)bh * CTX + q0) * HD;
    const float* kbase = k + (size_t)bh * CTX * HD;
    const float* vbase = v + (size_t)bh * CTX * HD;

    // Q A-fragments, scale folded (1/sqrt(64) = 0.125)
    uint32_t qa[8][4];
#pragma unroll
    for (int ks = 0; ks < 8; ks++) {
        const int kc = ks * 8;
        qa[ks][0] = f2tf(0.125f * qbase[(g)     * HD + kc + t]);
        qa[ks][1] = f2tf(0.125f * qbase[(g + 8) * HD + kc + t]);
        qa[ks][2] = f2tf(0.125f * qbase[(g)     * HD + kc + t + 4]);
        qa[ks][3] = f2tf(0.125f * qbase[(g + 8) * HD + kc + t + 4]);
    }

    float oacc[8][4];
#pragma unroll
    for (int ni = 0; ni < 8; ni++)
#pragma unroll
        for (int c = 0; c < 4; c++) oacc[ni][c] = 0.f;
    float m_lo = -1e30f, m_hi = -1e30f, l_lo = 0.f, l_hi = 0.f;

    for (int kt = 0; kt <= qt; kt++) {
        __syncthreads();
        // load K,V tiles (64x64 fp32 each), cvt to tf32 bits
#pragma unroll
        for (int i = 0; i < 8; i++) {
            const int it = tid + i * 128;
            const int row = it >> 4;
            const int f4 = it & 15;
            float4 kv4 = *(const float4*)(kbase + (size_t)(kt * 64 + row) * HD + f4 * 4);
            float4 vv4 = *(const float4*)(vbase + (size_t)(kt * 64 + row) * HD + f4 * 4);
            *(uint4*)(Ks + row * KSTR + f4 * 4) =
                make_uint4(f2tf(kv4.x), f2tf(kv4.y), f2tf(kv4.z), f2tf(kv4.w));
            *(uint4*)(Vs + row * KSTR + f4 * 4) =
                make_uint4(f2tf(vv4.x), f2tf(vv4.y), f2tf(vv4.z), f2tf(vv4.w));
        }
        __syncthreads();

        // S = Q K^T  (16 x 64 per warp)
        float sacc[8][4];
#pragma unroll
        for (int ni = 0; ni < 8; ni++)
#pragma unroll
            for (int c = 0; c < 4; c++) sacc[ni][c] = 0.f;

#pragma unroll
        for (int ks = 0; ks < 8; ks++) {
            const int kc = ks * 8;
#pragma unroll
            for (int ni = 0; ni < 8; ni++) {
                uint32_t b[2];
                b[0] = Ks[(ni * 8 + g) * KSTR + kc + t];
                b[1] = Ks[(ni * 8 + g) * KSTR + kc + t + 4];
                mma_tf32(sacc[ni], qa[ks], b);
            }
        }

        // causal mask (diagonal tile only)
        if (kt == qt) {
            const int r_lo = q0 + g, r_hi = r_lo + 8;
#pragma unroll
            for (int ni = 0; ni < 8; ni++) {
                const int c0 = kt * 64 + ni * 8 + 2 * t;
                if (c0 > r_lo)     sacc[ni][0] = -1e30f;
                if (c0 + 1 > r_lo) sacc[ni][1] = -1e30f;
                if (c0 > r_hi)     sacc[ni][2] = -1e30f;
                if (c0 + 1 > r_hi) sacc[ni][3] = -1e30f;
            }
        }

        // online softmax (rows lo/hi per thread; quad reduction over t)
        float rmx_lo = -1e30f, rmx_hi = -1e30f;
#pragma unroll
        for (int ni = 0; ni < 8; ni++) {
            rmx_lo = fmaxf(rmx_lo, fmaxf(sacc[ni][0], sacc[ni][1]));
            rmx_hi = fmaxf(rmx_hi, fmaxf(sacc[ni][2], sacc[ni][3]));
        }
        rmx_lo = fmaxf(rmx_lo, __shfl_xor_sync(0xffffffffu, rmx_lo, 1));
        rmx_lo = fmaxf(rmx_lo, __shfl_xor_sync(0xffffffffu, rmx_lo, 2));
        rmx_hi = fmaxf(rmx_hi, __shfl_xor_sync(0xffffffffu, rmx_hi, 1));
        rmx_hi = fmaxf(rmx_hi, __shfl_xor_sync(0xffffffffu, rmx_hi, 2));

        const float mn_lo = fmaxf(m_lo, rmx_lo);
        const float mn_hi = fmaxf(m_hi, rmx_hi);
        const float sc_lo = __expf(m_lo - mn_lo);
        const float sc_hi = __expf(m_hi - mn_hi);
        m_lo = mn_lo; m_hi = mn_hi;

        float rs_lo = 0.f, rs_hi = 0.f;
#pragma unroll
        for (int ni = 0; ni < 8; ni++) {
            sacc[ni][0] = __expf(sacc[ni][0] - mn_lo);
            sacc[ni][1] = __expf(sacc[ni][1] - mn_lo);
            sacc[ni][2] = __expf(sacc[ni][2] - mn_hi);
            sacc[ni][3] = __expf(sacc[ni][3] - mn_hi);
            rs_lo += sacc[ni][0] + sacc[ni][1];
            rs_hi += sacc[ni][2] + sacc[ni][3];
        }
        rs_lo += __shfl_xor_sync(0xffffffffu, rs_lo, 1);
        rs_lo += __shfl_xor_sync(0xffffffffu, rs_lo, 2);
        rs_hi += __shfl_xor_sync(0xffffffffu, rs_hi, 1);
        rs_hi += __shfl_xor_sync(0xffffffffu, rs_hi, 2);
        l_lo = l_lo * sc_lo + rs_lo;
        l_hi = l_hi * sc_hi + rs_hi;
#pragma unroll
        for (int ni = 0; ni < 8; ni++) {
            oacc[ni][0] *= sc_lo; oacc[ni][1] *= sc_lo;
            oacc[ni][2] *= sc_hi; oacc[ni][3] *= sc_hi;
        }

        // store P (tf32 bits) to per-warp smem region
        const int pr_lo = wid * 16 + g, pr_hi = pr_lo + 8;
#pragma unroll
        for (int ni = 0; ni < 8; ni++) {
            *(uint2*)(Ps + pr_lo * KSTR + ni * 8 + 2 * t) =
                make_uint2(f2tf(sacc[ni][0]), f2tf(sacc[ni][1]));
            *(uint2*)(Ps + pr_hi * KSTR + ni * 8 + 2 * t) =
                make_uint2(f2tf(sacc[ni][2]), f2tf(sacc[ni][3]));
        }
        __syncwarp();

        // O += P V   (A = P from smem, B = V col-fragments)
#pragma unroll
        for (int ks = 0; ks < 8; ks++) {
            const int kc = ks * 8;
            uint32_t pa[4];
            pa[0] = Ps[(wid * 16 + g) * KSTR + kc + t];
            pa[1] = Ps[(wid * 16 + g + 8) * KSTR + kc + t];
            pa[2] = Ps[(wid * 16 + g) * KSTR + kc + t + 4];
            pa[3] = Ps[(wid * 16 + g + 8) * KSTR + kc + t + 4];
#pragma unroll
            for (int ni = 0; ni < 8; ni++) {
                uint32_t b[2];
                b[0] = Vs[(kc + t) * KSTR + ni * 8 + g];
                b[1] = Vs[(kc + t + 4) * KSTR + ni * 8 + g];
                mma_tf32(oacc[ni], pa, b);
            }
        }
    }

    // normalize + write (B,T,N)
    const int b_ = bh >> 4;
    const int h  = bh & 15;
    const float inv_lo = 1.f / l_lo;
    const float inv_hi = 1.f / l_hi;
    const int t_lo = q0 + g, t_hi = t_lo + 8;
#pragma unroll
    for (int ni = 0; ni < 8; ni++) {
        const int col = h * HD + ni * 8 + 2 * t;
        *(float2*)(o + ((size_t)(b_ * CTX + t_lo)) * EMB + col) =
            make_float2(oacc[ni][0] * inv_lo, oacc[ni][1] * inv_lo);
        *(float2*)(o + ((size_t)(b_ * CTX + t_hi)) * EMB + col) =
            make_float2(oacc[ni][2] * inv_hi, oacc[ni][3] * inv_hi);
    }
}

// ---------------------------------------------------------------------------
extern "C" void kernel_launch(void* const* d_in, const int* in_sizes, int n_in,
                              void* d_out, int out_size) {
    const float* x  = (const float*)d_in[0];
    const float* Wq = (const float*)d_in[1];
    const float* bq = (const float*)d_in[2];
    const float* Wk = (const float*)d_in[3];
    const float* bk = (const float*)d_in[4];
    const float* Wv = (const float*)d_in[5];
    const float* bv = (const float*)d_in[6];
    const float* Wp = (const float*)d_in[7];
    const float* bp = (const float*)d_in[8];

    float *q, *k, *v, *a;
    cudaGetSymbolAddress((void**)&q, g_q);
    cudaGetSymbolAddress((void**)&k, g_k);
    cudaGetSymbolAddress((void**)&v, g_v);
    cudaGetSymbolAddress((void**)&a, g_a);

    cudaFuncSetAttribute(attn_kernel,
                         cudaFuncAttributeMaxDynamicSharedMemorySize, ATTN_SMEM);

    dim3 ggrid(EMB / 128, BT / 128);   // (8, 64)
    gemm_tc<1><<<ggrid, 256>>>(x, Wq, bq, q);
    gemm_tc<1><<<ggrid, 256>>>(x, Wk, bk, k);
    gemm_tc<1><<<ggrid, 256>>>(x, Wv, bv, v);

    attn_kernel<<<dim3(CTX / 64, 4 * NH), 128, ATTN_SMEM>>>(q, k, v, a);

    gemm_tc<0><<<ggrid, 256>>>(a, Wp, bp, (float*)d_out);
}

// round 4
// speedup vs baseline: 5.4763x; 1.1420x over previous
#include <cuda_runtime.h>
#include <cstdint>

#define CTX  2048
#define EMB  1024
#define NH   16
#define HD   64
#define BT   8192   // B*T

// Scratch (allocation-free rule: __device__ globals)
__device__ float g_q[BT * EMB];
__device__ float g_k[BT * EMB];
__device__ float g_v[BT * EMB];
__device__ float g_a[BT * EMB];

// ======================= helpers ===========================================
__device__ __forceinline__ uint32_t f2tf(float f) {
    uint32_t u;
    asm("cvt.rna.tf32.f32 %0, %1;" : "=r"(u) : "f"(f));
    return u;
}
// D(16x8,f32) += A(16x8,tf32,row) * B(8x8,tf32,col)
__device__ __forceinline__ void mma_tf32(float* d, const uint32_t* a,
                                         const uint32_t* b) {
    asm volatile(
        "mma.sync.aligned.m16n8k8.row.col.f32.tf32.tf32.f32 "
        "{%0,%1,%2,%3}, {%4,%5,%6,%7}, {%8,%9}, {%0,%1,%2,%3};"
        : "+f"(d[0]), "+f"(d[1]), "+f"(d[2]), "+f"(d[3])
        : "r"(a[0]), "r"(a[1]), "r"(a[2]), "r"(a[3]), "r"(b[0]), "r"(b[1]));
}
__device__ __forceinline__ uint32_t smem_u32(const void* p) {
    uint32_t a;
    asm("{ .reg .u64 t; cvta.to.shared.u64 t, %1; cvt.u32.u64 %0, t; }"
        : "=r"(a) : "l"(p));
    return a;
}
__device__ __forceinline__ void cp_async16(uint32_t dst, const void* src) {
    asm volatile("cp.async.cg.shared.global [%0], [%1], 16;"
                 :: "r"(dst), "l"(src));
}
#define CP_COMMIT() asm volatile("cp.async.commit_group;" ::: "memory")
#define CP_WAIT1()  asm volatile("cp.async.wait_group 1;" ::: "memory")

// ---------------------------------------------------------------------------
// GEMM core: C[m,n] = sum_k A[m,k] * W[n,k] + bias[n]
// 128x128 CTA tile, 256 thr / 8 warps, warp tile 64x32, k-chunks of 32.
// MODE 0: row-major out.  MODE 1: scatter to (B,H,T,D).
// ---------------------------------------------------------------------------
#define ASTRIDE 36

template <int MODE>
__device__ __forceinline__
void gemm_core(const float* __restrict__ A, const float* __restrict__ W,
               const float* __restrict__ bias, float* __restrict__ C,
               uint32_t* As, uint32_t* Bs, int m0, int n0) {
    const int tid  = threadIdx.x;
    const int wid  = tid >> 5;
    const int lane = tid & 31;
    const int g    = lane >> 2;
    const int t    = lane & 3;
    const int wm0  = (wid >> 2) * 64;
    const int wn0  = (wid & 3) * 32;

    float acc[4][4][4];
#pragma unroll
    for (int mi = 0; mi < 4; mi++)
#pragma unroll
        for (int ni = 0; ni < 4; ni++)
#pragma unroll
            for (int c = 0; c < 4; c++) acc[mi][ni][c] = 0.f;

    float4 ra[4], rb[4];
#pragma unroll
    for (int i = 0; i < 4; i++) {
        const int it = tid + i * 256;
        const int row = it >> 3;
        const int kv = it & 7;
        ra[i] = *(const float4*)(A + (size_t)(m0 + row) * EMB + kv * 4);
        rb[i] = *(const float4*)(W + (size_t)(n0 + row) * EMB + kv * 4);
    }

    for (int c = 0; c < 32; c++) {
        __syncthreads();
#pragma unroll
        for (int i = 0; i < 4; i++) {
            const int it = tid + i * 256;
            const int row = it >> 3;
            const int kv = it & 7;
            *(uint4*)(As + row * ASTRIDE + kv * 4) =
                make_uint4(f2tf(ra[i].x), f2tf(ra[i].y), f2tf(ra[i].z), f2tf(ra[i].w));
            *(uint4*)(Bs + row * ASTRIDE + kv * 4) =
                make_uint4(f2tf(rb[i].x), f2tf(rb[i].y), f2tf(rb[i].z), f2tf(rb[i].w));
        }
        __syncthreads();
        if (c < 31) {
            const int k0 = (c + 1) * 32;
#pragma unroll
            for (int i = 0; i < 4; i++) {
                const int it = tid + i * 256;
                const int row = it >> 3;
                const int kv = it & 7;
                ra[i] = *(const float4*)(A + (size_t)(m0 + row) * EMB + k0 + kv * 4);
                rb[i] = *(const float4*)(W + (size_t)(n0 + row) * EMB + k0 + kv * 4);
            }
        }
#pragma unroll
        for (int ks = 0; ks < 4; ks++) {
            const int kc = ks * 8;
            uint32_t afr[4][4];
#pragma unroll
            for (int mi = 0; mi < 4; mi++) {
                const int rb_ = wm0 + mi * 16;
                afr[mi][0] = As[(rb_ + g) * ASTRIDE + kc + t];
                afr[mi][1] = As[(rb_ + g + 8) * ASTRIDE + kc + t];
                afr[mi][2] = As[(rb_ + g) * ASTRIDE + kc + t + 4];
                afr[mi][3] = As[(rb_ + g + 8) * ASTRIDE + kc + t + 4];
            }
            uint32_t bfr[4][2];
#pragma unroll
            for (int ni = 0; ni < 4; ni++) {
                const int nb = wn0 + ni * 8;
                bfr[ni][0] = Bs[(nb + g) * ASTRIDE + kc + t];
                bfr[ni][1] = Bs[(nb + g) * ASTRIDE + kc + t + 4];
            }
#pragma unroll
            for (int mi = 0; mi < 4; mi++)
#pragma unroll
                for (int ni = 0; ni < 4; ni++)
                    mma_tf32(acc[mi][ni], afr[mi], bfr[ni]);
        }
    }

#pragma unroll
    for (int mi = 0; mi < 4; mi++) {
        const int r_lo = m0 + wm0 + mi * 16 + g;
        const int r_hi = r_lo + 8;
#pragma unroll
        for (int ni = 0; ni < 4; ni++) {
            const int n = n0 + wn0 + ni * 8 + 2 * t;
            const float2 b2 = *(const float2*)(bias + n);
            float2 lo = make_float2(acc[mi][ni][0] + b2.x, acc[mi][ni][1] + b2.y);
            float2 hi = make_float2(acc[mi][ni][2] + b2.x, acc[mi][ni][3] + b2.y);
            if (MODE == 0) {
                *(float2*)(C + (size_t)r_lo * EMB + n) = lo;
                *(float2*)(C + (size_t)r_hi * EMB + n) = hi;
            } else {
                const int h = n >> 6, d = n & 63;
                const int b1_ = r_lo >> 11, t1 = r_lo & 2047;
                const int b2_ = r_hi >> 11, t2 = r_hi & 2047;
                *(float2*)(C + (((size_t)(b1_ * NH + h) * CTX + t1) * HD + d)) = lo;
                *(float2*)(C + (((size_t)(b2_ * NH + h) * CTX + t2) * HD + d)) = hi;
            }
        }
    }
}

__global__ __launch_bounds__(256)
void gemm_proj(const float* __restrict__ A, const float* __restrict__ W,
               const float* __restrict__ bias, float* __restrict__ C) {
    __shared__ uint32_t As[128 * ASTRIDE];
    __shared__ uint32_t Bs[128 * ASTRIDE];
    gemm_core<0>(A, W, bias, C, As, Bs, blockIdx.y * 128, blockIdx.x * 128);
}

__global__ __launch_bounds__(256)
void gemm_qkv(const float* __restrict__ A,
              const float* __restrict__ W0, const float* __restrict__ b0,
              const float* __restrict__ W1, const float* __restrict__ b1,
              const float* __restrict__ W2, const float* __restrict__ b2,
              float* __restrict__ C0, float* __restrict__ C1,
              float* __restrict__ C2) {
    __shared__ uint32_t As[128 * ASTRIDE];
    __shared__ uint32_t Bs[128 * ASTRIDE];
    const int z = blockIdx.z;
    const float* W = (z == 0) ? W0 : (z == 1) ? W1 : W2;
    const float* b = (z == 0) ? b0 : (z == 1) ? b1 : b2;
    float* C = (z == 0) ? C0 : (z == 1) ? C1 : C2;
    gemm_core<1>(A, W, b, C, As, Bs, blockIdx.y * 128, blockIdx.x * 128);
}

// ---------------------------------------------------------------------------
// Flash attention (causal), mma.sync tf32.
// 128 queries/CTA, 4 warps x 32 queries (2 m-atoms), 64-key tiles.
// K/V: cp.async double-buffered raw f32 (HW tf32 truncation).
// Q in registers (rna, scale folded). P through smem (rna).
// ---------------------------------------------------------------------------
#define KSTR 68
#define ATTN_SMEM ((4 * 64 * KSTR + 128 * KSTR) * 4)

__global__ __launch_bounds__(128, 2)
void attn_kernel(const float* __restrict__ q, const float* __restrict__ k,
                 const float* __restrict__ v, float* __restrict__ o) {
    extern __shared__ uint32_t sm_[];
    uint32_t* Ps = sm_ + 4 * 64 * KSTR;
    const uint32_t sbase = smem_u32(sm_);

    const int tid  = threadIdx.x;
    const int wid  = tid >> 5;
    const int lane = tid & 31;
    const int g    = lane >> 2;
    const int t    = lane & 3;
    const int qt   = blockIdx.x;
    const int bh   = blockIdx.y;
    const int q0   = qt * 128 + wid * 32;
    const int qmax = q0 + 31;

    const float* qbase = q + ((size_t)bh * CTX + q0) * HD;
    const float* kbase = k + (size_t)bh * CTX * HD;
    const float* vbase = v + (size_t)bh * CTX * HD;

    // Q A-fragments (2 m-atoms), scale 1/8 folded
    uint32_t qa[2][8][4];
#pragma unroll
    for (int mi = 0; mi < 2; mi++)
#pragma unroll
        for (int ks = 0; ks < 8; ks++) {
            const int kc = ks * 8;
            const int r = mi * 16;
            qa[mi][ks][0] = f2tf(0.125f * qbase[(r + g)     * HD + kc + t]);
            qa[mi][ks][1] = f2tf(0.125f * qbase[(r + g + 8) * HD + kc + t]);
            qa[mi][ks][2] = f2tf(0.125f * qbase[(r + g)     * HD + kc + t + 4]);
            qa[mi][ks][3] = f2tf(0.125f * qbase[(r + g + 8) * HD + kc + t + 4]);
        }

    float oacc[2][8][4];
#pragma unroll
    for (int mi = 0; mi < 2; mi++)
#pragma unroll
        for (int ni = 0; ni < 8; ni++)
#pragma unroll
            for (int c = 0; c < 4; c++) oacc[mi][ni][c] = 0.f;
    float m_[2][2] = {{-1e30f, -1e30f}, {-1e30f, -1e30f}};
    float l_[2][2] = {{0.f, 0.f}, {0.f, 0.f}};

    const int ktmax = 2 * qt + 1;

    // async K/V tile producer
    auto issue = [&](int kt, int buf) {
#pragma unroll
        for (int i = 0; i < 8; i++) {
            const int it = tid + i * 128;
            const int row = it >> 4;
            const int f4 = it & 15;
            const uint32_t off = (row * KSTR + f4 * 4) * 4;
            cp_async16(sbase + buf * (64 * KSTR * 4) + off,
                       kbase + (size_t)(kt * 64 + row) * HD + f4 * 4);
            cp_async16(sbase + (2 + buf) * (64 * KSTR * 4) + off,
                       vbase + (size_t)(kt * 64 + row) * HD + f4 * 4);
        }
    };

    issue(0, 0);
    CP_COMMIT();

    for (int kt = 0; kt <= ktmax; kt++) {
        const int buf = kt & 1;
        if (kt < ktmax) issue(kt + 1, buf ^ 1);
        CP_COMMIT();
        CP_WAIT1();
        __syncthreads();

        if (kt * 64 <= qmax) {
            const uint32_t* Ks = sm_ + buf * 64 * KSTR;
            const uint32_t* Vs = sm_ + (2 + buf) * 64 * KSTR;

            // S = Q K^T
            float sacc[2][8][4];
#pragma unroll
            for (int mi = 0; mi < 2; mi++)
#pragma unroll
                for (int ni = 0; ni < 8; ni++)
#pragma unroll
                    for (int c = 0; c < 4; c++) sacc[mi][ni][c] = 0.f;

#pragma unroll
            for (int ks = 0; ks < 8; ks++) {
                const int kc = ks * 8;
#pragma unroll
                for (int ni = 0; ni < 8; ni++) {
                    uint32_t b[2];
                    b[0] = Ks[(ni * 8 + g) * KSTR + kc + t];
                    b[1] = Ks[(ni * 8 + g) * KSTR + kc + t + 4];
                    mma_tf32(sacc[0][ni], qa[0][ks], b);
                    mma_tf32(sacc[1][ni], qa[1][ks], b);
                }
            }

            // causal mask (only when tile overlaps diagonal for this warp)
            if (kt * 64 + 63 > q0) {
#pragma unroll
                for (int mi = 0; mi < 2; mi++) {
                    const int r_lo = q0 + mi * 16 + g;
                    const int r_hi = r_lo + 8;
#pragma unroll
                    for (int ni = 0; ni < 8; ni++) {
                        const int c0 = kt * 64 + ni * 8 + 2 * t;
                        if (c0 > r_lo)     sacc[mi][ni][0] = -1e30f;
                        if (c0 + 1 > r_lo) sacc[mi][ni][1] = -1e30f;
                        if (c0 > r_hi)     sacc[mi][ni][2] = -1e30f;
                        if (c0 + 1 > r_hi) sacc[mi][ni][3] = -1e30f;
                    }
                }
            }

            // online softmax per m-atom
#pragma unroll
            for (int mi = 0; mi < 2; mi++) {
                float rmx_lo = -1e30f, rmx_hi = -1e30f;
#pragma unroll
                for (int ni = 0; ni < 8; ni++) {
                    rmx_lo = fmaxf(rmx_lo, fmaxf(sacc[mi][ni][0], sacc[mi][ni][1]));
                    rmx_hi = fmaxf(rmx_hi, fmaxf(sacc[mi][ni][2], sacc[mi][ni][3]));
                }
                rmx_lo = fmaxf(rmx_lo, __shfl_xor_sync(0xffffffffu, rmx_lo, 1));
                rmx_lo = fmaxf(rmx_lo, __shfl_xor_sync(0xffffffffu, rmx_lo, 2));
                rmx_hi = fmaxf(rmx_hi, __shfl_xor_sync(0xffffffffu, rmx_hi, 1));
                rmx_hi = fmaxf(rmx_hi, __shfl_xor_sync(0xffffffffu, rmx_hi, 2));

                const float mn_lo = fmaxf(m_[mi][0], rmx_lo);
                const float mn_hi = fmaxf(m_[mi][1], rmx_hi);
                const float sc_lo = __expf(m_[mi][0] - mn_lo);
                const float sc_hi = __expf(m_[mi][1] - mn_hi);
                m_[mi][0] = mn_lo; m_[mi][1] = mn_hi;

                float rs_lo = 0.f, rs_hi = 0.f;
#pragma unroll
                for (int ni = 0; ni < 8; ni++) {
                    sacc[mi][ni][0] = __expf(sacc[mi][ni][0] - mn_lo);
                    sacc[mi][ni][1] = __expf(sacc[mi][ni][1] - mn_lo);
                    sacc[mi][ni][2] = __expf(sacc[mi][ni][2] - mn_hi);
                    sacc[mi][ni][3] = __expf(sacc[mi][ni][3] - mn_hi);
                    rs_lo += sacc[mi][ni][0] + sacc[mi][ni][1];
                    rs_hi += sacc[mi][ni][2] + sacc[mi][ni][3];
                }
                rs_lo += __shfl_xor_sync(0xffffffffu, rs_lo, 1);
                rs_lo += __shfl_xor_sync(0xffffffffu, rs_lo, 2);
                rs_hi += __shfl_xor_sync(0xffffffffu, rs_hi, 1);
                rs_hi += __shfl_xor_sync(0xffffffffu, rs_hi, 2);
                l_[mi][0] = l_[mi][0] * sc_lo + rs_lo;
                l_[mi][1] = l_[mi][1] * sc_hi + rs_hi;
#pragma unroll
                for (int ni = 0; ni < 8; ni++) {
                    oacc[mi][ni][0] *= sc_lo; oacc[mi][ni][1] *= sc_lo;
                    oacc[mi][ni][2] *= sc_hi; oacc[mi][ni][3] *= sc_hi;
                }

                // P store (rna tf32)
                const int pr_lo = wid * 32 + mi * 16 + g;
                const int pr_hi = pr_lo + 8;
#pragma unroll
                for (int ni = 0; ni < 8; ni++) {
                    *(uint2*)(Ps + pr_lo * KSTR + ni * 8 + 2 * t) =
                        make_uint2(f2tf(sacc[mi][ni][0]), f2tf(sacc[mi][ni][1]));
                    *(uint2*)(Ps + pr_hi * KSTR + ni * 8 + 2 * t) =
                        make_uint2(f2tf(sacc[mi][ni][2]), f2tf(sacc[mi][ni][3]));
                }
            }
            __syncwarp();

            // O += P V
#pragma unroll
            for (int ks = 0; ks < 8; ks++) {
                const int kc = ks * 8;
                uint32_t pa0[4], pa1[4];
                const int pb = wid * 32;
                pa0[0] = Ps[(pb + g) * KSTR + kc + t];
                pa0[1] = Ps[(pb + g + 8) * KSTR + kc + t];
                pa0[2] = Ps[(pb + g) * KSTR + kc + t + 4];
                pa0[3] = Ps[(pb + g + 8) * KSTR + kc + t + 4];
                pa1[0] = Ps[(pb + 16 + g) * KSTR + kc + t];
                pa1[1] = Ps[(pb + 16 + g + 8) * KSTR + kc + t];
                pa1[2] = Ps[(pb + 16 + g) * KSTR + kc + t + 4];
                pa1[3] = Ps[(pb + 16 + g + 8) * KSTR + kc + t + 4];
#pragma unroll
                for (int ni = 0; ni < 8; ni++) {
                    uint32_t b[2];
                    b[0] = Vs[(kc + t) * KSTR + ni * 8 + g];
                    b[1] = Vs[(kc + t + 4) * KSTR + ni * 8 + g];
                    mma_tf32(oacc[0][ni], pa0, b);
                    mma_tf32(oacc[1][ni], pa1, b);
                }
            }
        }
        __syncthreads();
    }

    // normalize + write (B,T,N)
    const int b_ = bh >> 4;
    const int h  = bh & 15;
#pragma unroll
    for (int mi = 0; mi < 2; mi++) {
        const float inv_lo = 1.f / l_[mi][0];
        const float inv_hi = 1.f / l_[mi][1];
        const int t_lo = q0 + mi * 16 + g;
        const int t_hi = t_lo + 8;
#pragma unroll
        for (int ni = 0; ni < 8; ni++) {
            const int col = h * HD + ni * 8 + 2 * t;
            *(float2*)(o + ((size_t)(b_ * CTX + t_lo)) * EMB + col) =
                make_float2(oacc[mi][ni][0] * inv_lo, oacc[mi][ni][1] * inv_lo);
            *(float2*)(o + ((size_t)(b_ * CTX + t_hi)) * EMB + col) =
                make_float2(oacc[mi][ni][2] * inv_hi, oacc[mi][ni][3] * inv_hi);
        }
    }
}

// ---------------------------------------------------------------------------
extern "C" void kernel_launch(void* const* d_in, const int* in_sizes, int n_in,
                              void* d_out, int out_size) {
    const float* x  = (const float*)d_in[0];
    const float* Wq = (const float*)d_in[1];
    const float* bq = (const float*)d_in[2];
    const float* Wk = (const float*)d_in[3];
    const float* bk = (const float*)d_in[4];
    const float* Wv = (const float*)d_in[5];
    const float* bv = (const float*)d_in[6];
    const float* Wp = (const float*)d_in[7];
    const float* bp = (const float*)d_in[8];

    float *q, *k, *v, *a;
    cudaGetSymbolAddress((void**)&q, g_q);
    cudaGetSymbolAddress((void**)&k, g_k);
    cudaGetSymbolAddress((void**)&v, g_v);
    cudaGetSymbolAddress((void**)&a, g_a);

    cudaFuncSetAttribute(attn_kernel,
                         cudaFuncAttributeMaxDynamicSharedMemorySize, ATTN_SMEM);

    gemm_qkv<<<dim3(EMB / 128, BT / 128, 3), 256>>>(
        x, Wq, bq, Wk, bk, Wv, bv, q, k, v);

    attn_kernel<<<dim3(CTX / 128, 4 * NH), 128, ATTN_SMEM>>>(q, k, v, a);

    gemm_proj<<<dim3(EMB / 128, BT / 128), 256>>>(a, Wp, bp, (float*)d_out);
}

// round 5
// speedup vs baseline: 5.6149x; 1.0253x over previous
#include <cuda_runtime.h>
#include <cstdint>

#define CTX  2048
#define EMB  1024
#define NH   16
#define HD   64
#define BT   8192   // B*T

// Scratch (allocation-free rule: __device__ globals)
__device__ float g_q[BT * EMB];
__device__ float g_k[BT * EMB];
__device__ float g_v[BT * EMB];
__device__ float g_a[BT * EMB];

// ======================= helpers ===========================================
__device__ __forceinline__ uint32_t f2tf(float f) {
    uint32_t u;
    asm("cvt.rna.tf32.f32 %0, %1;" : "=r"(u) : "f"(f));
    return u;
}
// D(16x8,f32) += A(16x8,tf32,row) * B(8x8,tf32,col)
__device__ __forceinline__ void mma_tf32(float* d, const uint32_t* a,
                                         const uint32_t* b) {
    asm volatile(
        "mma.sync.aligned.m16n8k8.row.col.f32.tf32.tf32.f32 "
        "{%0,%1,%2,%3}, {%4,%5,%6,%7}, {%8,%9}, {%0,%1,%2,%3};"
        : "+f"(d[0]), "+f"(d[1]), "+f"(d[2]), "+f"(d[3])
        : "r"(a[0]), "r"(a[1]), "r"(a[2]), "r"(a[3]), "r"(b[0]), "r"(b[1]));
}
__device__ __forceinline__ uint32_t smem_u32(const void* p) {
    uint32_t a;
    asm("{ .reg .u64 t; cvta.to.shared.u64 t, %1; cvt.u32.u64 %0, t; }"
        : "=r"(a) : "l"(p));
    return a;
}
__device__ __forceinline__ void cp_async16(uint32_t dst, const void* src) {
    asm volatile("cp.async.cg.shared.global [%0], [%1], 16;"
                 :: "r"(dst), "l"(src));
}
#define CP_COMMIT() asm volatile("cp.async.commit_group;" ::: "memory")
#define CP_WAIT1()  asm volatile("cp.async.wait_group 1;" ::: "memory")

// ---------------------------------------------------------------------------
// GEMM core: C[m,n] = sum_k A[m,k] * W[n,k] + bias[n]
// 128x128 CTA tile, 256 thr / 8 warps, warp tile 64x32, k-chunks of 32.
// cp.async 2-stage pipeline, raw f32 in smem, cvt.rna at fragment build.
// MODE 0: row-major out.  MODE 1: scatter to (B,H,T,D).
// ---------------------------------------------------------------------------
#define ASTRIDE 36
#define GTILE (128 * ASTRIDE)              // floats per tile per stage
#define GEMM_SMEM (4 * GTILE * 4)          // A[2] + B[2], bytes = 73728

template <int MODE>
__device__ __forceinline__
void gemm_core(const float* __restrict__ A, const float* __restrict__ W,
               const float* __restrict__ bias, float* __restrict__ C,
               float* sm, int m0, int n0) {
    const uint32_t sA = smem_u32(sm);
    const uint32_t sB = sA + 2 * GTILE * 4;

    const int tid  = threadIdx.x;
    const int wid  = tid >> 5;
    const int lane = tid & 31;
    const int g    = lane >> 2;
    const int t    = lane & 3;
    const int wm0  = (wid >> 2) * 64;
    const int wn0  = (wid & 3) * 32;

    float acc[4][4][4];
#pragma unroll
    for (int mi = 0; mi < 4; mi++)
#pragma unroll
        for (int ni = 0; ni < 4; ni++)
#pragma unroll
            for (int c = 0; c < 4; c++) acc[mi][ni][c] = 0.f;

    // per-thread fixed load slots
    const int row_ = tid >> 3;     // 0..31 base row (+32 per rep)
    const int kv_  = tid & 7;      // float4 index within 32-float chunk

    auto issue = [&](int c, int s) {
        const int k0 = c * 32;
#pragma unroll
        for (int i = 0; i < 4; i++) {
            const int row = row_ + i * 32;
            const uint32_t off = (s * GTILE + row * ASTRIDE + kv_ * 4) * 4;
            cp_async16(sA + off, A + (size_t)(m0 + row) * EMB + k0 + kv_ * 4);
            cp_async16(sB + off, W + (size_t)(n0 + row) * EMB + k0 + kv_ * 4);
        }
    };

    issue(0, 0);
    CP_COMMIT();

    for (int c = 0; c < 32; c++) {
        const int s = c & 1;
        __syncthreads();               // guard stage s^1 reuse
        if (c < 31) issue(c + 1, s ^ 1);
        CP_COMMIT();
        CP_WAIT1();                    // stage s data arrived
        __syncthreads();

        const float* Af = sm + s * GTILE;
        const float* Bf = sm + 2 * GTILE + s * GTILE;
#pragma unroll
        for (int ks = 0; ks < 4; ks++) {
            const int kc = ks * 8;
            uint32_t afr[4][4];
#pragma unroll
            for (int mi = 0; mi < 4; mi++) {
                const int rb_ = wm0 + mi * 16;
                afr[mi][0] = f2tf(Af[(rb_ + g) * ASTRIDE + kc + t]);
                afr[mi][1] = f2tf(Af[(rb_ + g + 8) * ASTRIDE + kc + t]);
                afr[mi][2] = f2tf(Af[(rb_ + g) * ASTRIDE + kc + t + 4]);
                afr[mi][3] = f2tf(Af[(rb_ + g + 8) * ASTRIDE + kc + t + 4]);
            }
            uint32_t bfr[4][2];
#pragma unroll
            for (int ni = 0; ni < 4; ni++) {
                const int nb = wn0 + ni * 8;
                bfr[ni][0] = f2tf(Bf[(nb + g) * ASTRIDE + kc + t]);
                bfr[ni][1] = f2tf(Bf[(nb + g) * ASTRIDE + kc + t + 4]);
            }
#pragma unroll
            for (int mi = 0; mi < 4; mi++)
#pragma unroll
                for (int ni = 0; ni < 4; ni++)
                    mma_tf32(acc[mi][ni], afr[mi], bfr[ni]);
        }
    }

#pragma unroll
    for (int mi = 0; mi < 4; mi++) {
        const int r_lo = m0 + wm0 + mi * 16 + g;
        const int r_hi = r_lo + 8;
#pragma unroll
        for (int ni = 0; ni < 4; ni++) {
            const int n = n0 + wn0 + ni * 8 + 2 * t;
            const float2 b2 = *(const float2*)(bias + n);
            float2 lo = make_float2(acc[mi][ni][0] + b2.x, acc[mi][ni][1] + b2.y);
            float2 hi = make_float2(acc[mi][ni][2] + b2.x, acc[mi][ni][3] + b2.y);
            if (MODE == 0) {
                *(float2*)(C + (size_t)r_lo * EMB + n) = lo;
                *(float2*)(C + (size_t)r_hi * EMB + n) = hi;
            } else {
                const int h = n >> 6, d = n & 63;
                const int b1_ = r_lo >> 11, t1 = r_lo & 2047;
                const int b2_ = r_hi >> 11, t2 = r_hi & 2047;
                *(float2*)(C + (((size_t)(b1_ * NH + h) * CTX + t1) * HD + d)) = lo;
                *(float2*)(C + (((size_t)(b2_ * NH + h) * CTX + t2) * HD + d)) = hi;
            }
        }
    }
}

__global__ __launch_bounds__(256, 2)
void gemm_proj(const float* __restrict__ A, const float* __restrict__ W,
               const float* __restrict__ bias, float* __restrict__ C) {
    extern __shared__ float smg[];
    gemm_core<0>(A, W, bias, C, smg, blockIdx.y * 128, blockIdx.x * 128);
}

__global__ __launch_bounds__(256, 2)
void gemm_qkv(const float* __restrict__ A,
              const float* __restrict__ W0, const float* __restrict__ b0,
              const float* __restrict__ W1, const float* __restrict__ b1,
              const float* __restrict__ W2, const float* __restrict__ b2,
              float* __restrict__ C0, float* __restrict__ C1,
              float* __restrict__ C2) {
    extern __shared__ float smg[];
    const int z = blockIdx.z;
    const float* W = (z == 0) ? W0 : (z == 1) ? W1 : W2;
    const float* b = (z == 0) ? b0 : (z == 1) ? b1 : b2;
    float* C = (z == 0) ? C0 : (z == 1) ? C1 : C2;
    gemm_core<1>(A, W, b, C, smg, blockIdx.y * 128, blockIdx.x * 128);
}

// ---------------------------------------------------------------------------
// Flash attention (causal), mma.sync tf32 — unchanged from R4.
// 128 queries/CTA, 4 warps x 32 queries, 64-key tiles, cp.async double buffer.
// ---------------------------------------------------------------------------
#define KSTR 68
#define ATTN_SMEM ((4 * 64 * KSTR + 128 * KSTR) * 4)

__global__ __launch_bounds__(128, 2)
void attn_kernel(const float* __restrict__ q, const float* __restrict__ k,
                 const float* __restrict__ v, float* __restrict__ o) {
    extern __shared__ uint32_t sm_[];
    uint32_t* Ps = sm_ + 4 * 64 * KSTR;
    const uint32_t sbase = smem_u32(sm_);

    const int tid  = threadIdx.x;
    const int wid  = tid >> 5;
    const int lane = tid & 31;
    const int g    = lane >> 2;
    const int t    = lane & 3;
    const int qt   = blockIdx.x;
    const int bh   = blockIdx.y;
    const int q0   = qt * 128 + wid * 32;
    const int qmax = q0 + 31;

    const float* qbase = q + ((size_t)bh * CTX + q0) * HD;
    const float* kbase = k + (size_t)bh * CTX * HD;
    const float* vbase = v + (size_t)bh * CTX * HD;

    uint32_t qa[2][8][4];
#pragma unroll
    for (int mi = 0; mi < 2; mi++)
#pragma unroll
        for (int ks = 0; ks < 8; ks++) {
            const int kc = ks * 8;
            const int r = mi * 16;
            qa[mi][ks][0] = f2tf(0.125f * qbase[(r + g)     * HD + kc + t]);
            qa[mi][ks][1] = f2tf(0.125f * qbase[(r + g + 8) * HD + kc + t]);
            qa[mi][ks][2] = f2tf(0.125f * qbase[(r + g)     * HD + kc + t + 4]);
            qa[mi][ks][3] = f2tf(0.125f * qbase[(r + g + 8) * HD + kc + t + 4]);
        }

    float oacc[2][8][4];
#pragma unroll
    for (int mi = 0; mi < 2; mi++)
#pragma unroll
        for (int ni = 0; ni < 8; ni++)
#pragma unroll
            for (int c = 0; c < 4; c++) oacc[mi][ni][c] = 0.f;
    float m_[2][2] = {{-1e30f, -1e30f}, {-1e30f, -1e30f}};
    float l_[2][2] = {{0.f, 0.f}, {0.f, 0.f}};

    const int ktmax = 2 * qt + 1;

    auto issue = [&](int kt, int buf) {
#pragma unroll
        for (int i = 0; i < 8; i++) {
            const int it = tid + i * 128;
            const int row = it >> 4;
            const int f4 = it & 15;
            const uint32_t off = (row * KSTR + f4 * 4) * 4;
            cp_async16(sbase + buf * (64 * KSTR * 4) + off,
                       kbase + (size_t)(kt * 64 + row) * HD + f4 * 4);
            cp_async16(sbase + (2 + buf) * (64 * KSTR * 4) + off,
                       vbase + (size_t)(kt * 64 + row) * HD + f4 * 4);
        }
    };

    issue(0, 0);
    CP_COMMIT();

    for (int kt = 0; kt <= ktmax; kt++) {
        const int buf = kt & 1;
        if (kt < ktmax) issue(kt + 1, buf ^ 1);
        CP_COMMIT();
        CP_WAIT1();
        __syncthreads();

        if (kt * 64 <= qmax) {
            const uint32_t* Ks = sm_ + buf * 64 * KSTR;
            const uint32_t* Vs = sm_ + (2 + buf) * 64 * KSTR;

            float sacc[2][8][4];
#pragma unroll
            for (int mi = 0; mi < 2; mi++)
#pragma unroll
                for (int ni = 0; ni < 8; ni++)
#pragma unroll
                    for (int c = 0; c < 4; c++) sacc[mi][ni][c] = 0.f;

#pragma unroll
            for (int ks = 0; ks < 8; ks++) {
                const int kc = ks * 8;
#pragma unroll
                for (int ni = 0; ni < 8; ni++) {
                    uint32_t b[2];
                    b[0] = Ks[(ni * 8 + g) * KSTR + kc + t];
                    b[1] = Ks[(ni * 8 + g) * KSTR + kc + t + 4];
                    mma_tf32(sacc[0][ni], qa[0][ks], b);
                    mma_tf32(sacc[1][ni], qa[1][ks], b);
                }
            }

            if (kt * 64 + 63 > q0) {
#pragma unroll
                for (int mi = 0; mi < 2; mi++) {
                    const int r_lo = q0 + mi * 16 + g;
                    const int r_hi = r_lo + 8;
#pragma unroll
                    for (int ni = 0; ni < 8; ni++) {
                        const int c0 = kt * 64 + ni * 8 + 2 * t;
                        if (c0 > r_lo)     sacc[mi][ni][0] = -1e30f;
                        if (c0 + 1 > r_lo) sacc[mi][ni][1] = -1e30f;
                        if (c0 > r_hi)     sacc[mi][ni][2] = -1e30f;
                        if (c0 + 1 > r_hi) sacc[mi][ni][3] = -1e30f;
                    }
                }
            }

#pragma unroll
            for (int mi = 0; mi < 2; mi++) {
                float rmx_lo = -1e30f, rmx_hi = -1e30f;
#pragma unroll
                for (int ni = 0; ni < 8; ni++) {
                    rmx_lo = fmaxf(rmx_lo, fmaxf(sacc[mi][ni][0], sacc[mi][ni][1]));
                    rmx_hi = fmaxf(rmx_hi, fmaxf(sacc[mi][ni][2], sacc[mi][ni][3]));
                }
                rmx_lo = fmaxf(rmx_lo, __shfl_xor_sync(0xffffffffu, rmx_lo, 1));
                rmx_lo = fmaxf(rmx_lo, __shfl_xor_sync(0xffffffffu, rmx_lo, 2));
                rmx_hi = fmaxf(rmx_hi, __shfl_xor_sync(0xffffffffu, rmx_hi, 1));
                rmx_hi = fmaxf(rmx_hi, __shfl_xor_sync(0xffffffffu, rmx_hi, 2));

                const float mn_lo = fmaxf(m_[mi][0], rmx_lo);
                const float mn_hi = fmaxf(m_[mi][1], rmx_hi);
                const float sc_lo = __expf(m_[mi][0] - mn_lo);
                const float sc_hi = __expf(m_[mi][1] - mn_hi);
                m_[mi][0] = mn_lo; m_[mi][1] = mn_hi;

                float rs_lo = 0.f, rs_hi = 0.f;
#pragma unroll
                for (int ni = 0; ni < 8; ni++) {
                    sacc[mi][ni][0] = __expf(sacc[mi][ni][0] - mn_lo);
                    sacc[mi][ni][1] = __expf(sacc[mi][ni][1] - mn_lo);
                    sacc[mi][ni][2] = __expf(sacc[mi][ni][2] - mn_hi);
                    sacc[mi][ni][3] = __expf(sacc[mi][ni][3] - mn_hi);
                    rs_lo += sacc[mi][ni][0] + sacc[mi][ni][1];
                    rs_hi += sacc[mi][ni][2] + sacc[mi][ni][3];
                }
                rs_lo += __shfl_xor_sync(0xffffffffu, rs_lo, 1);
                rs_lo += __shfl_xor_sync(0xffffffffu, rs_lo, 2);
                rs_hi += __shfl_xor_sync(0xffffffffu, rs_hi, 1);
                rs_hi += __shfl_xor_sync(0xffffffffu, rs_hi, 2);
                l_[mi][0] = l_[mi][0] * sc_lo + rs_lo;
                l_[mi][1] = l_[mi][1] * sc_hi + rs_hi;
#pragma unroll
                for (int ni = 0; ni < 8; ni++) {
                    oacc[mi][ni][0] *= sc_lo; oacc[mi][ni][1] *= sc_lo;
                    oacc[mi][ni][2] *= sc_hi; oacc[mi][ni][3] *= sc_hi;
                }

                const int pr_lo = wid * 32 + mi * 16 + g;
                const int pr_hi = pr_lo + 8;
#pragma unroll
                for (int ni = 0; ni < 8; ni++) {
                    *(uint2*)(Ps + pr_lo * KSTR + ni * 8 + 2 * t) =
                        make_uint2(f2tf(sacc[mi][ni][0]), f2tf(sacc[mi][ni][1]));
                    *(uint2*)(Ps + pr_hi * KSTR + ni * 8 + 2 * t) =
                        make_uint2(f2tf(sacc[mi][ni][2]), f2tf(sacc[mi][ni][3]));
                }
            }
            __syncwarp();

#pragma unroll
            for (int ks = 0; ks < 8; ks++) {
                const int kc = ks * 8;
                uint32_t pa0[4], pa1[4];
                const int pb = wid * 32;
                pa0[0] = Ps[(pb + g) * KSTR + kc + t];
                pa0[1] = Ps[(pb + g + 8) * KSTR + kc + t];
                pa0[2] = Ps[(pb + g) * KSTR + kc + t + 4];
                pa0[3] = Ps[(pb + g + 8) * KSTR + kc + t + 4];
                pa1[0] = Ps[(pb + 16 + g) * KSTR + kc + t];
                pa1[1] = Ps[(pb + 16 + g + 8) * KSTR + kc + t];
                pa1[2] = Ps[(pb + 16 + g) * KSTR + kc + t + 4];
                pa1[3] = Ps[(pb + 16 + g + 8) * KSTR + kc + t + 4];
#pragma unroll
                for (int ni = 0; ni < 8; ni++) {
                    uint32_t b[2];
                    b[0] = Vs[(kc + t) * KSTR + ni * 8 + g];
                    b[1] = Vs[(kc + t + 4) * KSTR + ni * 8 + g];
                    mma_tf32(oacc[0][ni], pa0, b);
                    mma_tf32(oacc[1][ni], pa1, b);
                }
            }
        }
        __syncthreads();
    }

    const int b_ = bh >> 4;
    const int h  = bh & 15;
#pragma unroll
    for (int mi = 0; mi < 2; mi++) {
        const float inv_lo = 1.f / l_[mi][0];
        const float inv_hi = 1.f / l_[mi][1];
        const int t_lo = q0 + mi * 16 + g;
        const int t_hi = t_lo + 8;
#pragma unroll
        for (int ni = 0; ni < 8; ni++) {
            const int col = h * HD + ni * 8 + 2 * t;
            *(float2*)(o + ((size_t)(b_ * CTX + t_lo)) * EMB + col) =
                make_float2(oacc[mi][ni][0] * inv_lo, oacc[mi][ni][1] * inv_lo);
            *(float2*)(o + ((size_t)(b_ * CTX + t_hi)) * EMB + col) =
                make_float2(oacc[mi][ni][2] * inv_hi, oacc[mi][ni][3] * inv_hi);
        }
    }
}

// ---------------------------------------------------------------------------
extern "C" void kernel_launch(void* const* d_in, const int* in_sizes, int n_in,
                              void* d_out, int out_size) {
    const float* x  = (const float*)d_in[0];
    const float* Wq = (const float*)d_in[1];
    const float* bq = (const float*)d_in[2];
    const float* Wk = (const float*)d_in[3];
    const float* bk = (const float*)d_in[4];
    const float* Wv = (const float*)d_in[5];
    const float* bv = (const float*)d_in[6];
    const float* Wp = (const float*)d_in[7];
    const float* bp = (const float*)d_in[8];

    float *q, *k, *v, *a;
    cudaGetSymbolAddress((void**)&q, g_q);
    cudaGetSymbolAddress((void**)&k, g_k);
    cudaGetSymbolAddress((void**)&v, g_v);
    cudaGetSymbolAddress((void**)&a, g_a);

    cudaFuncSetAttribute(gemm_qkv,
                         cudaFuncAttributeMaxDynamicSharedMemorySize, GEMM_SMEM);
    cudaFuncSetAttribute(gemm_proj,
                         cudaFuncAttributeMaxDynamicSharedMemorySize, GEMM_SMEM);
    cudaFuncSetAttribute(attn_kernel,
                         cudaFuncAttributeMaxDynamicSharedMemorySize, ATTN_SMEM);

    gemm_qkv<<<dim3(EMB / 128, BT / 128, 3), 256, GEMM_SMEM>>>(
        x, Wq, bq, Wk, bk, Wv, bv, q, k, v);

    attn_kernel<<<dim3(CTX / 128, 4 * NH), 128, ATTN_SMEM>>>(q, k, v, a);

    gemm_proj<<<dim3(EMB / 128, BT / 128), 256, GEMM_SMEM>>>(a, Wp, bp, (float*)d_out);
}

// round 6
// speedup vs baseline: 5.8936x; 1.0496x over previous
#include <cuda_runtime.h>
#include <cstdint>

#define CTX  2048
#define EMB  1024
#define NH   16
#define HD   64
#define BT   8192   // B*T

// Scratch (allocation-free rule: __device__ globals)
__device__ float g_q[BT * EMB];
__device__ float g_k[BT * EMB];
__device__ float g_v[BT * EMB];
__device__ float g_a[BT * EMB];

// ======================= helpers ===========================================
__device__ __forceinline__ uint32_t f2tf(float f) {
    uint32_t u;
    asm("cvt.rna.tf32.f32 %0, %1;" : "=r"(u) : "f"(f));
    return u;
}
// D(16x8,f32) += A(16x8,tf32,row) * B(8x8,tf32,col)
__device__ __forceinline__ void mma_tf32(float* d, const uint32_t* a,
                                         const uint32_t* b) {
    asm volatile(
        "mma.sync.aligned.m16n8k8.row.col.f32.tf32.tf32.f32 "
        "{%0,%1,%2,%3}, {%4,%5,%6,%7}, {%8,%9}, {%0,%1,%2,%3};"
        : "+f"(d[0]), "+f"(d[1]), "+f"(d[2]), "+f"(d[3])
        : "r"(a[0]), "r"(a[1]), "r"(a[2]), "r"(a[3]), "r"(b[0]), "r"(b[1]));
}
__device__ __forceinline__ uint32_t smem_u32(const void* p) {
    uint32_t a;
    asm("{ .reg .u64 t; cvta.to.shared.u64 t, %1; cvt.u32.u64 %0, t; }"
        : "=r"(a) : "l"(p));
    return a;
}
__device__ __forceinline__ void cp_async16(uint32_t dst, const void* src) {
    asm volatile("cp.async.cg.shared.global [%0], [%1], 16;"
                 :: "r"(dst), "l"(src));
}
#define CP_COMMIT() asm volatile("cp.async.commit_group;" ::: "memory")
#define CP_WAIT1()  asm volatile("cp.async.wait_group 1;" ::: "memory")

// ---------------------------------------------------------------------------
// GEMM core: C[m,n] = sum_k A[m,k] * W[n,k] + bias[n]
// 128x128 CTA tile, 128 thr / 4 warps, warp tile 64x64 (4 m-atoms x 8 n-atoms).
// K-chunks of 32, cp.async 2-stage pipeline, cvt.rna at fragment build.
// MODE 0: row-major out.  MODE 1: scatter to (B,H,T,D).
// ---------------------------------------------------------------------------
#define ASTRIDE 36
#define GTILE (128 * ASTRIDE)              // floats per tile per stage
#define GEMM_SMEM (4 * GTILE * 4)          // A[2] + B[2] = 73728 bytes

template <int MODE>
__device__ __forceinline__
void gemm_core(const float* __restrict__ A, const float* __restrict__ W,
               const float* __restrict__ bias, float* __restrict__ C,
               float* sm, int m0, int n0) {
    const uint32_t sA = smem_u32(sm);
    const uint32_t sB = sA + 2 * GTILE * 4;

    const int tid  = threadIdx.x;
    const int wid  = tid >> 5;
    const int lane = tid & 31;
    const int g    = lane >> 2;
    const int t    = lane & 3;
    const int wm0  = (wid >> 1) * 64;
    const int wn0  = (wid & 1) * 64;

    float acc[4][8][4];
#pragma unroll
    for (int mi = 0; mi < 4; mi++)
#pragma unroll
        for (int ni = 0; ni < 8; ni++)
#pragma unroll
            for (int c = 0; c < 4; c++) acc[mi][ni][c] = 0.f;

    // per-thread fixed load slots: 8 reps cover 128 rows x 8 float4
    const int row_ = tid >> 3;     // 0..15 base row (+16 per rep)
    const int kv_  = tid & 7;

    auto issue = [&](int c, int s) {
        const int k0 = c * 32;
#pragma unroll
        for (int i = 0; i < 8; i++) {
            const int row = row_ + i * 16;
            const uint32_t off = (s * GTILE + row * ASTRIDE + kv_ * 4) * 4;
            cp_async16(sA + off, A + (size_t)(m0 + row) * EMB + k0 + kv_ * 4);
            cp_async16(sB + off, W + (size_t)(n0 + row) * EMB + k0 + kv_ * 4);
        }
    };

    issue(0, 0);
    CP_COMMIT();

    for (int c = 0; c < 32; c++) {
        const int s = c & 1;
        __syncthreads();               // guard stage s^1 reuse
        if (c < 31) issue(c + 1, s ^ 1);
        CP_COMMIT();
        CP_WAIT1();                    // stage s data arrived
        __syncthreads();

        const float* Af = sm + s * GTILE;
        const float* Bf = sm + 2 * GTILE + s * GTILE;
#pragma unroll
        for (int ks = 0; ks < 4; ks++) {
            const int kc = ks * 8;
            uint32_t afr[4][4];
#pragma unroll
            for (int mi = 0; mi < 4; mi++) {
                const int rb_ = wm0 + mi * 16;
                afr[mi][0] = f2tf(Af[(rb_ + g) * ASTRIDE + kc + t]);
                afr[mi][1] = f2tf(Af[(rb_ + g + 8) * ASTRIDE + kc + t]);
                afr[mi][2] = f2tf(Af[(rb_ + g) * ASTRIDE + kc + t + 4]);
                afr[mi][3] = f2tf(Af[(rb_ + g + 8) * ASTRIDE + kc + t + 4]);
            }
            uint32_t bfr[8][2];
#pragma unroll
            for (int ni = 0; ni < 8; ni++) {
                const int nb = wn0 + ni * 8;
                bfr[ni][0] = f2tf(Bf[(nb + g) * ASTRIDE + kc + t]);
                bfr[ni][1] = f2tf(Bf[(nb + g) * ASTRIDE + kc + t + 4]);
            }
#pragma unroll
            for (int mi = 0; mi < 4; mi++)
#pragma unroll
                for (int ni = 0; ni < 8; ni++)
                    mma_tf32(acc[mi][ni], afr[mi], bfr[ni]);
        }
    }

#pragma unroll
    for (int mi = 0; mi < 4; mi++) {
        const int r_lo = m0 + wm0 + mi * 16 + g;
        const int r_hi = r_lo + 8;
#pragma unroll
        for (int ni = 0; ni < 8; ni++) {
            const int n = n0 + wn0 + ni * 8 + 2 * t;
            const float2 b2 = *(const float2*)(bias + n);
            float2 lo = make_float2(acc[mi][ni][0] + b2.x, acc[mi][ni][1] + b2.y);
            float2 hi = make_float2(acc[mi][ni][2] + b2.x, acc[mi][ni][3] + b2.y);
            if (MODE == 0) {
                *(float2*)(C + (size_t)r_lo * EMB + n) = lo;
                *(float2*)(C + (size_t)r_hi * EMB + n) = hi;
            } else {
                const int h = n >> 6, d = n & 63;
                const int b1_ = r_lo >> 11, t1 = r_lo & 2047;
                const int b2_ = r_hi >> 11, t2 = r_hi & 2047;
                *(float2*)(C + (((size_t)(b1_ * NH + h) * CTX + t1) * HD + d)) = lo;
                *(float2*)(C + (((size_t)(b2_ * NH + h) * CTX + t2) * HD + d)) = hi;
            }
        }
    }
}

__global__ __launch_bounds__(128, 2)
void gemm_proj(const float* __restrict__ A, const float* __restrict__ W,
               const float* __restrict__ bias, float* __restrict__ C) {
    extern __shared__ float smg[];
    gemm_core<0>(A, W, bias, C, smg, blockIdx.y * 128, blockIdx.x * 128);
}

__global__ __launch_bounds__(128, 2)
void gemm_qkv(const float* __restrict__ A,
              const float* __restrict__ W0, const float* __restrict__ b0,
              const float* __restrict__ W1, const float* __restrict__ b1,
              const float* __restrict__ W2, const float* __restrict__ b2,
              float* __restrict__ C0, float* __restrict__ C1,
              float* __restrict__ C2) {
    extern __shared__ float smg[];
    const int z = blockIdx.z;
    const float* W = (z == 0) ? W0 : (z == 1) ? W1 : W2;
    const float* b = (z == 0) ? b0 : (z == 1) ? b1 : b2;
    float* C = (z == 0) ? C0 : (z == 1) ? C1 : C2;
    gemm_core<1>(A, W, b, C, smg, blockIdx.y * 128, blockIdx.x * 128);
}

// ---------------------------------------------------------------------------
// Flash attention (causal), mma.sync tf32 — unchanged from R5.
// ---------------------------------------------------------------------------
#define KSTR 68
#define ATTN_SMEM ((4 * 64 * KSTR + 128 * KSTR) * 4)

__global__ __launch_bounds__(128, 2)
void attn_kernel(const float* __restrict__ q, const float* __restrict__ k,
                 const float* __restrict__ v, float* __restrict__ o) {
    extern __shared__ uint32_t sm_[];
    uint32_t* Ps = sm_ + 4 * 64 * KSTR;
    const uint32_t sbase = smem_u32(sm_);

    const int tid  = threadIdx.x;
    const int wid  = tid >> 5;
    const int lane = tid & 31;
    const int g    = lane >> 2;
    const int t    = lane & 3;
    const int qt   = blockIdx.x;
    const int bh   = blockIdx.y;
    const int q0   = qt * 128 + wid * 32;
    const int qmax = q0 + 31;

    const float* qbase = q + ((size_t)bh * CTX + q0) * HD;
    const float* kbase = k + (size_t)bh * CTX * HD;
    const float* vbase = v + (size_t)bh * CTX * HD;

    uint32_t qa[2][8][4];
#pragma unroll
    for (int mi = 0; mi < 2; mi++)
#pragma unroll
        for (int ks = 0; ks < 8; ks++) {
            const int kc = ks * 8;
            const int r = mi * 16;
            qa[mi][ks][0] = f2tf(0.125f * qbase[(r + g)     * HD + kc + t]);
            qa[mi][ks][1] = f2tf(0.125f * qbase[(r + g + 8) * HD + kc + t]);
            qa[mi][ks][2] = f2tf(0.125f * qbase[(r + g)     * HD + kc + t + 4]);
            qa[mi][ks][3] = f2tf(0.125f * qbase[(r + g + 8) * HD + kc + t + 4]);
        }

    float oacc[2][8][4];
#pragma unroll
    for (int mi = 0; mi < 2; mi++)
#pragma unroll
        for (int ni = 0; ni < 8; ni++)
#pragma unroll
            for (int c = 0; c < 4; c++) oacc[mi][ni][c] = 0.f;
    float m_[2][2] = {{-1e30f, -1e30f}, {-1e30f, -1e30f}};
    float l_[2][2] = {{0.f, 0.f}, {0.f, 0.f}};

    const int ktmax = 2 * qt + 1;

    auto issue = [&](int kt, int buf) {
#pragma unroll
        for (int i = 0; i < 8; i++) {
            const int it = tid + i * 128;
            const int row = it >> 4;
            const int f4 = it & 15;
            const uint32_t off = (row * KSTR + f4 * 4) * 4;
            cp_async16(sbase + buf * (64 * KSTR * 4) + off,
                       kbase + (size_t)(kt * 64 + row) * HD + f4 * 4);
            cp_async16(sbase + (2 + buf) * (64 * KSTR * 4) + off,
                       vbase + (size_t)(kt * 64 + row) * HD + f4 * 4);
        }
    };

    issue(0, 0);
    CP_COMMIT();

    for (int kt = 0; kt <= ktmax; kt++) {
        const int buf = kt & 1;
        if (kt < ktmax) issue(kt + 1, buf ^ 1);
        CP_COMMIT();
        CP_WAIT1();
        __syncthreads();

        if (kt * 64 <= qmax) {
            const uint32_t* Ks = sm_ + buf * 64 * KSTR;
            const uint32_t* Vs = sm_ + (2 + buf) * 64 * KSTR;

            float sacc[2][8][4];
#pragma unroll
            for (int mi = 0; mi < 2; mi++)
#pragma unroll
                for (int ni = 0; ni < 8; ni++)
#pragma unroll
                    for (int c = 0; c < 4; c++) sacc[mi][ni][c] = 0.f;

#pragma unroll
            for (int ks = 0; ks < 8; ks++) {
                const int kc = ks * 8;
#pragma unroll
                for (int ni = 0; ni < 8; ni++) {
                    uint32_t b[2];
                    b[0] = Ks[(ni * 8 + g) * KSTR + kc + t];
                    b[1] = Ks[(ni * 8 + g) * KSTR + kc + t + 4];
                    mma_tf32(sacc[0][ni], qa[0][ks], b);
                    mma_tf32(sacc[1][ni], qa[1][ks], b);
                }
            }

            if (kt * 64 + 63 > q0) {
#pragma unroll
                for (int mi = 0; mi < 2; mi++) {
                    const int r_lo = q0 + mi * 16 + g;
                    const int r_hi = r_lo + 8;
#pragma unroll
                    for (int ni = 0; ni < 8; ni++) {
                        const int c0 = kt * 64 + ni * 8 + 2 * t;
                        if (c0 > r_lo)     sacc[mi][ni][0] = -1e30f;
                        if (c0 + 1 > r_lo) sacc[mi][ni][1] = -1e30f;
                        if (c0 > r_hi)     sacc[mi][ni][2] = -1e30f;
                        if (c0 + 1 > r_hi) sacc[mi][ni][3] = -1e30f;
                    }
                }
            }

#pragma unroll
            for (int mi = 0; mi < 2; mi++) {
                float rmx_lo = -1e30f, rmx_hi = -1e30f;
#pragma unroll
                for (int ni = 0; ni < 8; ni++) {
                    rmx_lo = fmaxf(rmx_lo, fmaxf(sacc[mi][ni][0], sacc[mi][ni][1]));
                    rmx_hi = fmaxf(rmx_hi, fmaxf(sacc[mi][ni][2], sacc[mi][ni][3]));
                }
                rmx_lo = fmaxf(rmx_lo, __shfl_xor_sync(0xffffffffu, rmx_lo, 1));
                rmx_lo = fmaxf(rmx_lo, __shfl_xor_sync(0xffffffffu, rmx_lo, 2));
                rmx_hi = fmaxf(rmx_hi, __shfl_xor_sync(0xffffffffu, rmx_hi, 1));
                rmx_hi = fmaxf(rmx_hi, __shfl_xor_sync(0xffffffffu, rmx_hi, 2));

                const float mn_lo = fmaxf(m_[mi][0], rmx_lo);
                const float mn_hi = fmaxf(m_[mi][1], rmx_hi);
                const float sc_lo = __expf(m_[mi][0] - mn_lo);
                const float sc_hi = __expf(m_[mi][1] - mn_hi);
                m_[mi][0] = mn_lo; m_[mi][1] = mn_hi;

                float rs_lo = 0.f, rs_hi = 0.f;
#pragma unroll
                for (int ni = 0; ni < 8; ni++) {
                    sacc[mi][ni][0] = __expf(sacc[mi][ni][0] - mn_lo);
                    sacc[mi][ni][1] = __expf(sacc[mi][ni][1] - mn_lo);
                    sacc[mi][ni][2] = __expf(sacc[mi][ni][2] - mn_hi);
                    sacc[mi][ni][3] = __expf(sacc[mi][ni][3] - mn_hi);
                    rs_lo += sacc[mi][ni][0] + sacc[mi][ni][1];
                    rs_hi += sacc[mi][ni][2] + sacc[mi][ni][3];
                }
                rs_lo += __shfl_xor_sync(0xffffffffu, rs_lo, 1);
                rs_lo += __shfl_xor_sync(0xffffffffu, rs_lo, 2);
                rs_hi += __shfl_xor_sync(0xffffffffu, rs_hi, 1);
                rs_hi += __shfl_xor_sync(0xffffffffu, rs_hi, 2);
                l_[mi][0] = l_[mi][0] * sc_lo + rs_lo;
                l_[mi][1] = l_[mi][1] * sc_hi + rs_hi;
#pragma unroll
                for (int ni = 0; ni < 8; ni++) {
                    oacc[mi][ni][0] *= sc_lo; oacc[mi][ni][1] *= sc_lo;
                    oacc[mi][ni][2] *= sc_hi; oacc[mi][ni][3] *= sc_hi;
                }

                const int pr_lo = wid * 32 + mi * 16 + g;
                const int pr_hi = pr_lo + 8;
#pragma unroll
                for (int ni = 0; ni < 8; ni++) {
                    *(uint2*)(Ps + pr_lo * KSTR + ni * 8 + 2 * t) =
                        make_uint2(f2tf(sacc[mi][ni][0]), f2tf(sacc[mi][ni][1]));
                    *(uint2*)(Ps + pr_hi * KSTR + ni * 8 + 2 * t) =
                        make_uint2(f2tf(sacc[mi][ni][2]), f2tf(sacc[mi][ni][3]));
                }
            }
            __syncwarp();

#pragma unroll
            for (int ks = 0; ks < 8; ks++) {
                const int kc = ks * 8;
                uint32_t pa0[4], pa1[4];
                const int pb = wid * 32;
                pa0[0] = Ps[(pb + g) * KSTR + kc + t];
                pa0[1] = Ps[(pb + g + 8) * KSTR + kc + t];
                pa0[2] = Ps[(pb + g) * KSTR + kc + t + 4];
                pa0[3] = Ps[(pb + g + 8) * KSTR + kc + t + 4];
                pa1[0] = Ps[(pb + 16 + g) * KSTR + kc + t];
                pa1[1] = Ps[(pb + 16 + g + 8) * KSTR + kc + t];
                pa1[2] = Ps[(pb + 16 + g) * KSTR + kc + t + 4];
                pa1[3] = Ps[(pb + 16 + g + 8) * KSTR + kc + t + 4];
#pragma unroll
                for (int ni = 0; ni < 8; ni++) {
                    uint32_t b[2];
                    b[0] = Vs[(kc + t) * KSTR + ni * 8 + g];
                    b[1] = Vs[(kc + t + 4) * KSTR + ni * 8 + g];
                    mma_tf32(oacc[0][ni], pa0, b);
                    mma_tf32(oacc[1][ni], pa1, b);
                }
            }
        }
        __syncthreads();
    }

    const int b_ = bh >> 4;
    const int h  = bh & 15;
#pragma unroll
    for (int mi = 0; mi < 2; mi++) {
        const float inv_lo = 1.f / l_[mi][0];
        const float inv_hi = 1.f / l_[mi][1];
        const int t_lo = q0 + mi * 16 + g;
        const int t_hi = t_lo + 8;
#pragma unroll
        for (int ni = 0; ni < 8; ni++) {
            const int col = h * HD + ni * 8 + 2 * t;
            *(float2*)(o + ((size_t)(b_ * CTX + t_lo)) * EMB + col) =
                make_float2(oacc[mi][ni][0] * inv_lo, oacc[mi][ni][1] * inv_lo);
            *(float2*)(o + ((size_t)(b_ * CTX + t_hi)) * EMB + col) =
                make_float2(oacc[mi][ni][2] * inv_hi, oacc[mi][ni][3] * inv_hi);
        }
    }
}

// ---------------------------------------------------------------------------
extern "C" void kernel_launch(void* const* d_in, const int* in_sizes, int n_in,
                              void* d_out, int out_size) {
    const float* x  = (const float*)d_in[0];
    const float* Wq = (const float*)d_in[1];
    const float* bq = (const float*)d_in[2];
    const float* Wk = (const float*)d_in[3];
    const float* bk = (const float*)d_in[4];
    const float* Wv = (const float*)d_in[5];
    const float* bv = (const float*)d_in[6];
    const float* Wp = (const float*)d_in[7];
    const float* bp = (const float*)d_in[8];

    float *q, *k, *v, *a;
    cudaGetSymbolAddress((void**)&q, g_q);
    cudaGetSymbolAddress((void**)&k, g_k);
    cudaGetSymbolAddress((void**)&v, g_v);
    cudaGetSymbolAddress((void**)&a, g_a);

    cudaFuncSetAttribute(gemm_qkv,
                         cudaFuncAttributeMaxDynamicSharedMemorySize, GEMM_SMEM);
    cudaFuncSetAttribute(gemm_proj,
                         cudaFuncAttributeMaxDynamicSharedMemorySize, GEMM_SMEM);
    cudaFuncSetAttribute(attn_kernel,
                         cudaFuncAttributeMaxDynamicSharedMemorySize, ATTN_SMEM);

    gemm_qkv<<<dim3(EMB / 128, BT / 128, 3), 128, GEMM_SMEM>>>(
        x, Wq, bq, Wk, bk, Wv, bv, q, k, v);

    attn_kernel<<<dim3(CTX / 128, 4 * NH), 128, ATTN_SMEM>>>(q, k, v, a);

    gemm_proj<<<dim3(EMB / 128, BT / 128), 128, GEMM_SMEM>>>(a, Wp, bp, (float*)d_out);
}